// round 1
// baseline (speedup 1.0000x reference)
#include <cuda_runtime.h>
#include <math.h>

// LSTMDecoder: B=64, H=1024, 2 layers, T=128 autoregressive steps.
// Per-step kernels captured into the graph:
//   step t: lstm_kernel(l=0)  [+ fused FC for step t-1]
//           lstm_kernel(l=1)
// plus one init kernel and one final FC-only call (t=128 trick).
// GEMMs via mma.sync.m16n8k8 tf32 with RNA rounding (zero-mean error).

#define BATCH 64
#define HID   1024
#define TSTEPS 128
#define NT    8        // hidden units per gate-block
#define KT    32       // K-chunk

// Persistent state (device globals — no allocation).
// g_h[layer][parity][B*H] : ping-pong hidden state buffers
// g_c[layer][B*H]         : cell state (block-private per unit -> in-place OK)
__device__ float g_h[2][2][BATCH * HID];
__device__ float g_c[2][BATCH * HID];

__device__ __forceinline__ float rna_tf32(float x) {
    unsigned u;
    asm("cvt.rna.tf32.f32 %0, %1;" : "=r"(u) : "f"(x));
    return __uint_as_float(u);
}

__device__ __forceinline__ void mma_tf32(float d[4],
                                         unsigned a0, unsigned a1, unsigned a2, unsigned a3,
                                         unsigned b0, unsigned b1) {
    asm volatile(
        "mma.sync.aligned.m16n8k8.row.col.f32.tf32.tf32.f32 "
        "{%0,%1,%2,%3}, {%4,%5,%6,%7}, {%8,%9}, {%0,%1,%2,%3};"
        : "+f"(d[0]), "+f"(d[1]), "+f"(d[2]), "+f"(d[3])
        : "r"(a0), "r"(a1), "r"(a2), "r"(a3), "r"(b0), "r"(b1));
}

__device__ __forceinline__ float sigmoidf_(float x) {
    return 1.0f / (1.0f + __expf(-x));
}

__global__ void init_state() {
    int i = blockIdx.x * blockDim.x + threadIdx.x;
    int stride = gridDim.x * blockDim.x;
    float* ph = &g_h[0][0][0];
    for (int k = i; k < 2 * 2 * BATCH * HID; k += stride) ph[k] = 0.0f;
    float* pc = &g_c[0][0];
    for (int k = i; k < 2 * BATCH * HID; k += stride) pc[k] = 0.0f;
}

// One LSTM layer step (+ optionally fused FC for the PREVIOUS step, which
// reads the same x as layer-0 of this step).
//   blocks [0, nGate)        : gate blocks, NT=8 units each -> nGate = 128
//   blocks [nGate, nGate+32) : FC blocks, 32 cols each (only when fused)
__global__ __launch_bounds__(256, 1) void lstm_kernel(
    int l, int t,
    const float* __restrict__ x_ext,
    const float* __restrict__ Wih,  const float* __restrict__ Whh,
    const float* __restrict__ bih,  const float* __restrict__ bhh,
    const float* __restrict__ Wfc,  const float* __restrict__ bfc,
    float* __restrict__ out, int nGate)
{
    __shared__ float Asx[BATCH][KT + 1];
    __shared__ float Ash[BATCH][KT + 1];
    __shared__ float Wsx[4 * NT][KT + 1];
    __shared__ float Wsh[4 * NT][KT + 1];
    __shared__ float red[4][32][17];

    const int tid  = threadIdx.x;
    const int warp = tid >> 5;
    const int lane = tid & 31;
    const int p = t & 1;

    // Input x pointer: layer0 reads prev step's layer1 output; layer1 reads
    // layer0's output of this step (already written — stream ordering).
    const float* xp = (l == 0)
        ? ((t == 0) ? x_ext : &g_h[1][p][0])
        : &g_h[0][1 - p][0];

    if (blockIdx.x >= nGate) {
        // ---------------- FC path: out[t-1] = x @ W_fc^T + b_fc -------------
        const int fcb = blockIdx.x - nGate;
        const int j0 = fcb * 32;
        float* out_fc = out + (size_t)(t - 1) * BATCH * HID;
        const int wgrp = warp >> 2;   // 0: cols [j0,j0+16), 1: [j0+16,j0+32)
        const int w4   = warp & 3;

        float acc[2][4];
        #pragma unroll
        for (int a = 0; a < 2; a++)
            #pragma unroll
            for (int b = 0; b < 4; b++) acc[a][b] = 0.0f;

        for (int kc = 0; kc < HID / KT; kc++) {
            const int k0 = kc * KT;
            #pragma unroll
            for (int i = 0; i < 8; i++) {
                int idx = tid + i * 256;
                int r = idx >> 5, c = idx & 31;
                Asx[r][c] = rna_tf32(xp[r * HID + k0 + c]);
            }
            #pragma unroll
            for (int i = 0; i < 4; i++) {
                int idx = tid + i * 256;
                int n = idx >> 5, c = idx & 31;
                Wsx[n][c] = rna_tf32(Wfc[(size_t)(j0 + n) * HID + k0 + c]);
            }
            __syncthreads();

            const int r0 = w4 * 16 + (lane >> 2);
            #pragma unroll
            for (int ks = 0; ks < 4; ks++) {
                const int ka = ks * 8 + (lane & 3);
                unsigned a0 = __float_as_uint(Asx[r0][ka]);
                unsigned a1 = __float_as_uint(Asx[r0 + 8][ka]);
                unsigned a2 = __float_as_uint(Asx[r0][ka + 4]);
                unsigned a3 = __float_as_uint(Asx[r0 + 8][ka + 4]);
                #pragma unroll
                for (int nt = 0; nt < 2; nt++) {
                    const int nb = wgrp * 16 + nt * 8 + (lane >> 2);
                    unsigned b0 = __float_as_uint(Wsx[nb][ka]);
                    unsigned b1 = __float_as_uint(Wsx[nb][ka + 4]);
                    mma_tf32(acc[nt], a0, a1, a2, a3, b0, b1);
                }
            }
            __syncthreads();
        }

        const int r0 = w4 * 16 + (lane >> 2);
        const int cb = (lane & 3) * 2;
        #pragma unroll
        for (int nt = 0; nt < 2; nt++)
            #pragma unroll
            for (int rr = 0; rr < 2; rr++)
                #pragma unroll
                for (int cc = 0; cc < 2; cc++) {
                    int b = r0 + rr * 8;
                    int col = j0 + wgrp * 16 + nt * 8 + cb + cc;
                    out_fc[(size_t)b * HID + col] = acc[nt][rr * 2 + cc] + bfc[col];
                }
        return;
    }

    // ------------------------- gate path -----------------------------------
    const int j0 = blockIdx.x * NT;
    const float* hin  = &g_h[l][p][0];
    float*       hout = &g_h[l][1 - p][0];
    float*       cs   = &g_c[l][0];
    const float* Wih_l = Wih + (size_t)l * 4 * HID * HID;
    const float* Whh_l = Whh + (size_t)l * 4 * HID * HID;
    const float* bih_l = bih + (size_t)l * 4 * HID;
    const float* bhh_l = bhh + (size_t)l * 4 * HID;

    float acc[4][4];
    #pragma unroll
    for (int q = 0; q < 4; q++)
        #pragma unroll
        for (int r = 0; r < 4; r++) acc[q][r] = 0.0f;

    const int w4 = warp & 3;

    for (int kc = 0; kc < HID / KT; kc++) {
        const int k0 = kc * KT;
        // cooperative loads, RNA-rounded to tf32
        #pragma unroll
        for (int i = 0; i < 8; i++) {
            int idx = tid + i * 256;
            int r = idx >> 5, c = idx & 31;
            Asx[r][c] = rna_tf32(xp[r * HID + k0 + c]);
            Ash[r][c] = rna_tf32(hin[r * HID + k0 + c]);
        }
        #pragma unroll
        for (int i = 0; i < 4; i++) {
            int idx = tid + i * 256;
            int n = idx >> 5, c = idx & 31;
            size_t grow = (size_t)((n >> 3) * HID + j0 + (n & 7));
            Wsx[n][c] = rna_tf32(Wih_l[grow * HID + k0 + c]);
            Wsh[n][c] = rna_tf32(Whh_l[grow * HID + k0 + c]);
        }
        __syncthreads();

        const float (*A)[KT + 1]  = (warp < 4) ? Asx : Ash;
        const float (*Wt)[KT + 1] = (warp < 4) ? Wsx : Wsh;
        const int r0 = w4 * 16 + (lane >> 2);
        #pragma unroll
        for (int ks = 0; ks < 4; ks++) {
            const int ka = ks * 8 + (lane & 3);
            unsigned a0 = __float_as_uint(A[r0][ka]);
            unsigned a1 = __float_as_uint(A[r0 + 8][ka]);
            unsigned a2 = __float_as_uint(A[r0][ka + 4]);
            unsigned a3 = __float_as_uint(A[r0 + 8][ka + 4]);
            #pragma unroll
            for (int q = 0; q < 4; q++) {
                const int nb = q * 8 + (lane >> 2);
                unsigned b0 = __float_as_uint(Wt[nb][ka]);
                unsigned b1 = __float_as_uint(Wt[nb][ka + 4]);
                mma_tf32(acc[q], a0, a1, a2, a3, b0, b1);
            }
        }
        __syncthreads();
    }

    // cross-phase reduction: warps 4-7 (h-part) -> warps 0-3 (x-part)
    if (warp >= 4) {
        #pragma unroll
        for (int q = 0; q < 4; q++)
            #pragma unroll
            for (int k = 0; k < 4; k++)
                red[warp - 4][lane][q * 4 + k] = acc[q][k];
    }
    __syncthreads();
    if (warp < 4) {
        #pragma unroll
        for (int q = 0; q < 4; q++)
            #pragma unroll
            for (int k = 0; k < 4; k++)
                acc[q][k] += red[warp][lane][q * 4 + k];

        // Epilogue: each thread holds i,f,g,o for 2 rows x 2 unit-cols.
        const int r0 = w4 * 16 + (lane >> 2);
        const int cb = (lane & 3) * 2;
        #pragma unroll
        for (int rr = 0; rr < 2; rr++) {
            const int b = r0 + rr * 8;
            #pragma unroll
            for (int cc = 0; cc < 2; cc++) {
                const int j = j0 + cb + cc;
                const int k = rr * 2 + cc;
                float iv = acc[0][k] + bih_l[0 * HID + j] + bhh_l[0 * HID + j];
                float fv = acc[1][k] + bih_l[1 * HID + j] + bhh_l[1 * HID + j];
                float gv = acc[2][k] + bih_l[2 * HID + j] + bhh_l[2 * HID + j];
                float ov = acc[3][k] + bih_l[3 * HID + j] + bhh_l[3 * HID + j];
                float ig = sigmoidf_(iv);
                float fg = sigmoidf_(fv);
                float gg = tanhf(gv);
                float og = sigmoidf_(ov);
                float cn = fg * cs[(size_t)b * HID + j] + ig * gg;
                cs[(size_t)b * HID + j] = cn;
                hout[(size_t)b * HID + j] = og * tanhf(cn);
            }
        }
    }
}

extern "C" void kernel_launch(void* const* d_in, const int* in_sizes, int n_in,
                              void* d_out, int out_size) {
    const float* h0   = (const float*)d_in[0];
    const float* Wih  = (const float*)d_in[1];
    const float* Whh  = (const float*)d_in[2];
    const float* bih  = (const float*)d_in[3];
    const float* bhh  = (const float*)d_in[4];
    const float* Wfc  = (const float*)d_in[5];
    const float* bfc  = (const float*)d_in[6];
    float* out = (float*)d_out;

    const int NGATE = HID / NT;  // 128 gate blocks

    init_state<<<256, 256>>>();

    for (int t = 0; t < TSTEPS; t++) {
        // layer 0 (+ fused FC of step t-1 when t>0)
        int grid0 = NGATE + ((t > 0) ? 32 : 0);
        lstm_kernel<<<grid0, 256>>>(0, t, h0, Wih, Whh, bih, bhh, Wfc, bfc, out, NGATE);
        // layer 1
        lstm_kernel<<<NGATE, 256>>>(1, t, h0, Wih, Whh, bih, bhh, Wfc, bfc, out, NGATE);
    }
    // final FC for step T-1: t=128 makes xp = g_h[1][0] (state after step 127)
    lstm_kernel<<<32, 256>>>(0, TSTEPS, h0, Wih, Whh, bih, bhh, Wfc, bfc, out, 0);
}

// round 3
// speedup vs baseline: 6.4027x; 6.4027x over previous
#include <cuda_runtime.h>
#include <cuda_fp16.h>
#include <math.h>

// Persistent-kernel LSTM decoder. B=64, H=1024, L=2, T=128.
// 128 CTAs (1/SM), grid barrier between layer phases.
// fp16 mma.m16n8k16 GEMMs; W_hh + W_fc SMEM-resident; W_ih + activations
// streamed from L2 with double-buffered cp.async.
// R2 fix: B fragments loaded with NON-trans ldmatrix ([n][k] storage already
// matches the B fragment layout: reg = two consecutive k at one n).

#define BATCH   64
#define HID     1024
#define TSTEPS  128
#define NCTA    128
#define THREADS 256
#define SA      136    // streamed act chunk row stride (halfs)
#define SW      136    // streamed weight chunk row stride (halfs)
#define SR      1032   // resident weight row stride (halfs)
#define KC      128    // K chunk

// ---------------- device globals (pre-permuted fp16 weights + state) -------
__device__ __half g_Wih_p[2 * NCTA * 32 * HID];   // [l][cta][pn][k]
__device__ __half g_Whh_p[2 * NCTA * 32 * HID];
__device__ __half g_Wfc_p[NCTA * 8 * HID];        // [cta][u][k]
__device__ __half g_hbuf[4 * BATCH * HID];        // [l*2+parity][b][h]
__device__ __half g_x0[BATCH * HID];
__device__ unsigned g_bar;

// ---------------- small asm helpers ---------------------------------------
__device__ __forceinline__ unsigned sptr(const void* p) {
    return (unsigned)__cvta_generic_to_shared(p);
}
__device__ __forceinline__ void cp16(void* s, const void* g) {
    asm volatile("cp.async.ca.shared.global [%0], [%1], 16;"
                 :: "r"(sptr(s)), "l"(g));
}
__device__ __forceinline__ void cp_commit() {
    asm volatile("cp.async.commit_group;");
}
template<int N> __device__ __forceinline__ void cp_wait() {
    asm volatile("cp.async.wait_group %0;" :: "n"(N));
}
__device__ __forceinline__ void ldsm_x4(unsigned &r0, unsigned &r1, unsigned &r2, unsigned &r3, unsigned a) {
    asm volatile("ldmatrix.sync.aligned.m8n8.x4.shared.b16 {%0,%1,%2,%3}, [%4];"
                 : "=r"(r0), "=r"(r1), "=r"(r2), "=r"(r3) : "r"(a));
}
__device__ __forceinline__ void ldsm_x2(unsigned &r0, unsigned &r1, unsigned a) {
    asm volatile("ldmatrix.sync.aligned.m8n8.x2.shared.b16 {%0,%1}, [%2];"
                 : "=r"(r0), "=r"(r1) : "r"(a));
}
__device__ __forceinline__ void hmma(float d[4], unsigned a0, unsigned a1, unsigned a2, unsigned a3,
                                     unsigned b0, unsigned b1) {
    asm volatile("mma.sync.aligned.m16n8k16.row.col.f32.f16.f16.f32 "
                 "{%0,%1,%2,%3},{%4,%5,%6,%7},{%8,%9},{%0,%1,%2,%3};"
                 : "+f"(d[0]), "+f"(d[1]), "+f"(d[2]), "+f"(d[3])
                 : "r"(a0), "r"(a1), "r"(a2), "r"(a3), "r"(b0), "r"(b1));
}
__device__ __forceinline__ float sig_(float x) { return 1.0f / (1.0f + __expf(-x)); }

// ---------------- prep kernels ---------------------------------------------
// permuted col index pn -> (gate, unit):
//   nn=pn&15; half=nn>>3; a=(nn&7)>>1; s=nn&1; gate=half*2+s; unit=(pn>>4)*4+a
__global__ void prep_gatew(const float* __restrict__ Wih, const float* __restrict__ Whh) {
    const int total = 2 * NCTA * 32 * HID;
    for (int e = blockIdx.x * blockDim.x + threadIdx.x; e < total; e += gridDim.x * blockDim.x) {
        int k = e & (HID - 1);
        int pn = (e >> 10) & 31;
        int cta = (e >> 15) & (NCTA - 1);
        int l = e >> 22;
        int nn = pn & 15, half = nn >> 3, a = (nn & 7) >> 1, s = nn & 1;
        int gate = half * 2 + s, unit = (pn >> 4) * 4 + a;
        size_t src = (size_t)l * 4 * HID * HID + (size_t)(gate * HID + cta * 8 + unit) * HID + k;
        g_Wih_p[e] = __float2half_rn(Wih[src]);
        g_Whh_p[e] = __float2half_rn(Whh[src]);
    }
}
__global__ void prep_misc(const float* __restrict__ h0, const float* __restrict__ Wfc) {
    int i = blockIdx.x * blockDim.x + threadIdx.x;
    int stride = gridDim.x * blockDim.x;
    for (int e = i; e < NCTA * 8 * HID; e += stride) {
        int k = e & (HID - 1);
        int u = (e >> 10) & 7;
        int cta = e >> 13;
        g_Wfc_p[e] = __float2half_rn(Wfc[(size_t)(cta * 8 + u) * HID + k]);
    }
    for (int e = i; e < BATCH * HID; e += stride) g_x0[e] = __float2half_rn(h0[e]);
    for (int e = i; e < 4 * BATCH * HID; e += stride) g_hbuf[e] = __float2half_rn(0.0f);
    if (i == 0) g_bar = 0;
}

// ---------------- grid barrier ---------------------------------------------
__device__ __forceinline__ void gbar(unsigned target) {
    __threadfence();
    __syncthreads();
    if (threadIdx.x == 0) {
        atomicAdd(&g_bar, 1u);
        unsigned v;
        do {
            asm volatile("ld.acquire.gpu.u32 %0, [%1];" : "=r"(v) : "l"(&g_bar));
        } while (v < target);
    }
    __syncthreads();
}

// ---------------- staging ---------------------------------------------------
__device__ __forceinline__ void stage_act(__half* dst, const __half* src, int k0, int tid) {
    #pragma unroll
    for (int i = 0; i < 4; i++) {
        int e = tid + i * THREADS;          // 1024 ops: 64 rows x 16 segs
        int r = e >> 4, sg = e & 15;
        cp16(dst + r * SA + sg * 8, src + r * HID + k0 + sg * 8);
    }
}
__device__ __forceinline__ void stage_w(__half* dst, const __half* src, int k0, int tid) {
    #pragma unroll
    for (int i = 0; i < 2; i++) {
        int e = tid + i * THREADS;          // 512 ops: 32 rows x 16 segs
        int r = e >> 4, sg = e & 15;
        cp16(dst + r * SW + sg * 8, src + r * HID + k0 + sg * 8);
    }
}

// ---------------- main persistent kernel ------------------------------------
__global__ __launch_bounds__(THREADS, 1) void lstm_persist(
    const float* __restrict__ bih, const float* __restrict__ bhh,
    const float* __restrict__ bfc, float* __restrict__ out)
{
    extern __shared__ __align__(16) unsigned char smem_raw[];
    __half* whhS  = (__half*)smem_raw;            // [2][32][SR]
    __half* wfcS  = whhS + 2 * 32 * SR;           // [8][SR]
    __half* xbufS = wfcS + 8 * SR;                // [2][64][SA]
    __half* wbufS = xbufS + 2 * 64 * SA;          // [2][32][SW]
    float*  cS    = (float*)(wbufS + 2 * 32 * SW);// [2][64][8]
    float*  biasS = cS + 2 * 64 * 8;              // [2][32]
    float*  fcbS  = biasS + 64;                   // [8]

    const int tid  = threadIdx.x;
    const int warp = tid >> 5;
    const int lane = tid & 31;
    const int wm   = warp & 3;     // M-tile
    const int wn   = warp >> 2;    // N-tile (unit group)
    const int cta  = blockIdx.x;
    const int j0   = cta * 8;

    // ---- load resident weights (Whh both layers + Wfc slice) ----
    for (int l = 0; l < 2; l++) {
        const __half* src = g_Whh_p + (size_t)(l * NCTA + cta) * 32 * HID;
        for (int i = 0; i < 16; i++) {
            int e = tid + i * THREADS;      // 4096 ops: 32 rows x 128 segs
            int r = e >> 7, sg = e & 127;
            cp16(whhS + l * 32 * SR + r * SR + sg * 8, src + r * HID + sg * 8);
        }
    }
    {
        const __half* src = g_Wfc_p + (size_t)cta * 8 * HID;
        for (int i = 0; i < 4; i++) {
            int e = tid + i * THREADS;      // 1024 ops: 8 rows x 128 segs
            int r = e >> 7, sg = e & 127;
            cp16(wfcS + r * SR + sg * 8, src + r * HID + sg * 8);
        }
    }
    cp_commit();
    // ---- biases / cell state ----
    if (tid < 64) {
        int l = tid >> 5, pn = tid & 31;
        int nn = pn & 15, half = nn >> 3, a = (nn & 7) >> 1, s = nn & 1;
        int gate = half * 2 + s, unit = (pn >> 4) * 4 + a;
        int row = gate * HID + j0 + unit;
        biasS[l * 32 + pn] = bih[l * 4 * HID + row] + bhh[l * 4 * HID + row];
    }
    if (tid < 8) fcbS[tid] = bfc[j0 + tid];
    #pragma unroll
    for (int i = 0; i < 4; i++) cS[tid + i * THREADS] = 0.0f;
    cp_wait<0>();
    __syncthreads();

    // precomputed shared addresses (bytes)
    const unsigned xb0 = sptr(xbufS) + ((wm * 16 + (lane & 15)) * SA + (lane >> 4) * 8) * 2;
    const unsigned xb1 = xb0 + 64 * SA * 2;
    const unsigned wb0 = sptr(wbufS) + ((wn * 16 + (lane & 15)) * SW + (lane >> 4) * 8) * 2;
    const unsigned wb1 = wb0 + 32 * SW * 2;
    const unsigned whA[2] = {
        sptr(whhS) + ((wn * 16 + (lane & 15)) * SR + (lane >> 4) * 8) * 2,
        sptr(whhS) + ((32 + wn * 16 + (lane & 15)) * SR + (lane >> 4) * 8) * 2 };
    const unsigned fcA = sptr(wfcS) + (((lane & 7)) * SR + ((lane >> 3) & 1) * 8) * 2;

    unsigned barTarget = 0;
    const int r = lane >> 2, a4 = lane & 3;
    const int uloc = wn * 4 + a4;

    for (int t = 0; t < TSTEPS; t++) {
        const int p = t & 1, q = p ^ 1;
        #pragma unroll 1
        for (int l = 0; l < 2; l++) {
            const __half* xsrc = (l == 0)
                ? ((t == 0) ? g_x0 : g_hbuf + (2 + q) * BATCH * HID)
                : g_hbuf + (0 + p) * BATCH * HID;
            const __half* hsrc = g_hbuf + (l * 2 + q) * BATCH * HID;
            __half* hdst = g_hbuf + (l * 2 + p) * BATCH * HID;
            const __half* wsrc = g_Wih_p + (size_t)(l * NCTA + cta) * 32 * HID;
            const bool do_fc = (l == 0) && (t > 0) && (wn == 0);

            float acc0[4] = {0, 0, 0, 0}, acc1[4] = {0, 0, 0, 0}, fca[4] = {0, 0, 0, 0};

            // ===== part 1: x @ Wih (streamed) [+ FC vs resident Wfc] =====
            stage_act(xbufS, xsrc, 0, tid);
            stage_w(wbufS, wsrc, 0, tid);
            cp_commit();
            #pragma unroll 1
            for (int kc = 0; kc < HID / KC; kc++) {
                if (kc + 1 < HID / KC) {
                    stage_act(xbufS + ((kc + 1) & 1) * 64 * SA, xsrc, (kc + 1) * KC, tid);
                    stage_w(wbufS + ((kc + 1) & 1) * 32 * SW, wsrc, (kc + 1) * KC, tid);
                    cp_commit();
                    cp_wait<1>();
                } else cp_wait<0>();
                __syncthreads();
                const unsigned xb = (kc & 1) ? xb1 : xb0;
                const unsigned wb = (kc & 1) ? wb1 : wb0;
                #pragma unroll
                for (int k16 = 0; k16 < KC / 16; k16++) {
                    unsigned a0, a1, a2, a3, b0, b1, b2, b3;
                    ldsm_x4(a0, a1, a2, a3, xb + k16 * 32);
                    ldsm_x4(b0, b1, b2, b3, wb + k16 * 32);
                    hmma(acc0, a0, a1, a2, a3, b0, b2);
                    hmma(acc1, a0, a1, a2, a3, b1, b3);
                    if (do_fc) {
                        unsigned f0, f1;
                        ldsm_x2(f0, f1, fcA + (kc * KC + k16 * 16) * 2);
                        hmma(fca, a0, a1, a2, a3, f0, f1);
                    }
                }
                __syncthreads();
            }

            // ===== part 2: h_rec @ Whh (resident) =====
            stage_act(xbufS, hsrc, 0, tid);
            cp_commit();
            #pragma unroll 1
            for (int kc = 0; kc < HID / KC; kc++) {
                if (kc + 1 < HID / KC) {
                    stage_act(xbufS + ((kc + 1) & 1) * 64 * SA, hsrc, (kc + 1) * KC, tid);
                    cp_commit();
                    cp_wait<1>();
                } else cp_wait<0>();
                __syncthreads();
                const unsigned xb = (kc & 1) ? xb1 : xb0;
                #pragma unroll
                for (int k16 = 0; k16 < KC / 16; k16++) {
                    unsigned a0, a1, a2, a3, b0, b1, b2, b3;
                    ldsm_x4(a0, a1, a2, a3, xb + k16 * 32);
                    ldsm_x4(b0, b1, b2, b3, whA[l] + (kc * KC + k16 * 16) * 2);
                    hmma(acc0, a0, a1, a2, a3, b0, b2);
                    hmma(acc1, a0, a1, a2, a3, b1, b3);
                }
                __syncthreads();
            }

            // ===== epilogue: register-local cell update =====
            float* crow = cS + l * 64 * 8;
            #pragma unroll
            for (int rp = 0; rp < 2; rp++) {
                int b = wm * 16 + r + rp * 8;
                float iv = acc0[rp * 2 + 0] + biasS[l * 32 + wn * 16 + a4 * 2 + 0];
                float fv = acc0[rp * 2 + 1] + biasS[l * 32 + wn * 16 + a4 * 2 + 1];
                float gv = acc1[rp * 2 + 0] + biasS[l * 32 + wn * 16 + 8 + a4 * 2 + 0];
                float ov = acc1[rp * 2 + 1] + biasS[l * 32 + wn * 16 + 8 + a4 * 2 + 1];
                float cn = sig_(fv) * crow[b * 8 + uloc] + sig_(iv) * tanhf(gv);
                crow[b * 8 + uloc] = cn;
                hdst[b * HID + j0 + uloc] = __float2half_rn(sig_(ov) * tanhf(cn));
            }
            if (do_fc) {
                float* op = out + (size_t)(t - 1) * BATCH * HID;
                #pragma unroll
                for (int rp = 0; rp < 2; rp++) {
                    int b = wm * 16 + r + rp * 8;
                    op[b * HID + j0 + a4 * 2 + 0] = fca[rp * 2 + 0] + fcbS[a4 * 2 + 0];
                    op[b * HID + j0 + a4 * 2 + 1] = fca[rp * 2 + 1] + fcbS[a4 * 2 + 1];
                }
            }
            barTarget += NCTA;
            gbar(barTarget);
        }
    }

    // ===== final FC for t = T-1 (x = h1 written at t=127, parity 1) =====
    {
        const __half* xsrc = g_hbuf + (2 + 1) * BATCH * HID;
        float fca[4] = {0, 0, 0, 0};
        stage_act(xbufS, xsrc, 0, tid);
        cp_commit();
        #pragma unroll 1
        for (int kc = 0; kc < HID / KC; kc++) {
            if (kc + 1 < HID / KC) {
                stage_act(xbufS + ((kc + 1) & 1) * 64 * SA, xsrc, (kc + 1) * KC, tid);
                cp_commit();
                cp_wait<1>();
            } else cp_wait<0>();
            __syncthreads();
            if (wn == 0) {
                const unsigned xb = (kc & 1) ? xb1 : xb0;
                #pragma unroll
                for (int k16 = 0; k16 < KC / 16; k16++) {
                    unsigned a0, a1, a2, a3, f0, f1;
                    ldsm_x4(a0, a1, a2, a3, xb + k16 * 32);
                    ldsm_x2(f0, f1, fcA + (kc * KC + k16 * 16) * 2);
                    hmma(fca, a0, a1, a2, a3, f0, f1);
                }
            }
            __syncthreads();
        }
        if (wn == 0) {
            float* op = out + (size_t)(TSTEPS - 1) * BATCH * HID;
            #pragma unroll
            for (int rp = 0; rp < 2; rp++) {
                int b = wm * 16 + r + rp * 8;
                op[b * HID + j0 + a4 * 2 + 0] = fca[rp * 2 + 0] + fcbS[a4 * 2 + 0];
                op[b * HID + j0 + a4 * 2 + 1] = fca[rp * 2 + 1] + fcbS[a4 * 2 + 1];
            }
        }
    }
}

// ---------------- host launch -----------------------------------------------
extern "C" void kernel_launch(void* const* d_in, const int* in_sizes, int n_in,
                              void* d_out, int out_size) {
    const float* h0  = (const float*)d_in[0];
    const float* Wih = (const float*)d_in[1];
    const float* Whh = (const float*)d_in[2];
    const float* bih = (const float*)d_in[3];
    const float* bhh = (const float*)d_in[4];
    const float* Wfc = (const float*)d_in[5];
    const float* bfc = (const float*)d_in[6];
    float* out = (float*)d_out;

    const int smem = (2 * 32 * SR + 8 * SR + 2 * 64 * SA + 2 * 32 * SW) * 2
                   + (2 * 64 * 8 + 64 + 8) * 4;
    cudaFuncSetAttribute(lstm_persist, cudaFuncAttributeMaxDynamicSharedMemorySize, smem);

    prep_gatew<<<2048, 256>>>(Wih, Whh);
    prep_misc<<<512, 256>>>(h0, Wfc);
    lstm_persist<<<NCTA, THREADS, smem>>>(bih, bhh, bfc, out);
}

// round 4
// speedup vs baseline: 6.7604x; 1.0559x over previous
#include <cuda_runtime.h>
#include <cuda_fp16.h>
#include <math.h>

// Persistent-kernel LSTM decoder. B=64, H=1024, L=2, T=128.
// 128 CTAs (1/SM), split arrive/wait grid barrier between layer phases.
// Phase order: recurrent GEMM (h@Whh, resident, needs NO fresh barrier)
//              -> barrier wait (hidden behind recurrent GEMM)
//              -> input GEMM (x@Wih streamed) + FC (k-split across warps)
//              -> epilogue (register-local cell update) -> arrive.
// fp16 mma.m16n8k16, 4 independent accumulator chains (even/odd k16).

#define BATCH   64
#define HID     1024
#define TSTEPS  128
#define NCTA    128
#define THREADS 256
#define SA      136    // streamed act chunk row stride (halfs)
#define SW      136    // streamed weight chunk row stride (halfs)
#define SR      1032   // resident weight row stride (halfs)
#define KC      128    // K chunk

// ---------------- device globals (pre-permuted fp16 weights + state) -------
__device__ __half g_Wih_p[2 * NCTA * 32 * HID];   // [l][cta][pn][k]
__device__ __half g_Whh_p[2 * NCTA * 32 * HID];
__device__ __half g_Wfc_p[NCTA * 8 * HID];        // [cta][u][k]
__device__ __half g_hbuf[4 * BATCH * HID];        // [l*2+parity][b][h]
__device__ __half g_x0[BATCH * HID];
__device__ unsigned g_bar;

// ---------------- small asm helpers ---------------------------------------
__device__ __forceinline__ unsigned sptr(const void* p) {
    return (unsigned)__cvta_generic_to_shared(p);
}
__device__ __forceinline__ void cp16(void* s, const void* g) {      // weights (.ca)
    asm volatile("cp.async.ca.shared.global [%0], [%1], 16;" :: "r"(sptr(s)), "l"(g));
}
__device__ __forceinline__ void cp16cg(void* s, const void* g) {    // acts (.cg, L1-bypass)
    asm volatile("cp.async.cg.shared.global [%0], [%1], 16;" :: "r"(sptr(s)), "l"(g));
}
__device__ __forceinline__ void cp_commit() {
    asm volatile("cp.async.commit_group;");
}
template<int N> __device__ __forceinline__ void cp_wait() {
    asm volatile("cp.async.wait_group %0;" :: "n"(N));
}
__device__ __forceinline__ void ldsm_x4(unsigned &r0, unsigned &r1, unsigned &r2, unsigned &r3, unsigned a) {
    asm volatile("ldmatrix.sync.aligned.m8n8.x4.shared.b16 {%0,%1,%2,%3}, [%4];"
                 : "=r"(r0), "=r"(r1), "=r"(r2), "=r"(r3) : "r"(a));
}
__device__ __forceinline__ void ldsm_x2(unsigned &r0, unsigned &r1, unsigned a) {
    asm volatile("ldmatrix.sync.aligned.m8n8.x2.shared.b16 {%0,%1}, [%2];"
                 : "=r"(r0), "=r"(r1) : "r"(a));
}
__device__ __forceinline__ void hmma(float d[4], unsigned a0, unsigned a1, unsigned a2, unsigned a3,
                                     unsigned b0, unsigned b1) {
    asm volatile("mma.sync.aligned.m16n8k16.row.col.f32.f16.f16.f32 "
                 "{%0,%1,%2,%3},{%4,%5,%6,%7},{%8,%9},{%0,%1,%2,%3};"
                 : "+f"(d[0]), "+f"(d[1]), "+f"(d[2]), "+f"(d[3])
                 : "r"(a0), "r"(a1), "r"(a2), "r"(a3), "r"(b0), "r"(b1));
}
__device__ __forceinline__ float sig_(float x) { return 1.0f / (1.0f + __expf(-x)); }

// ---------------- prep kernels ---------------------------------------------
// permuted col index pn -> (gate, unit):
//   nn=pn&15; half=nn>>3; a=(nn&7)>>1; s=nn&1; gate=half*2+s; unit=(pn>>4)*4+a
__global__ void prep_gatew(const float* __restrict__ Wih, const float* __restrict__ Whh) {
    const int total = 2 * NCTA * 32 * HID;
    for (int e = blockIdx.x * blockDim.x + threadIdx.x; e < total; e += gridDim.x * blockDim.x) {
        int k = e & (HID - 1);
        int pn = (e >> 10) & 31;
        int cta = (e >> 15) & (NCTA - 1);
        int l = e >> 22;
        int nn = pn & 15, half = nn >> 3, a = (nn & 7) >> 1, s = nn & 1;
        int gate = half * 2 + s, unit = (pn >> 4) * 4 + a;
        size_t src = (size_t)l * 4 * HID * HID + (size_t)(gate * HID + cta * 8 + unit) * HID + k;
        g_Wih_p[e] = __float2half_rn(Wih[src]);
        g_Whh_p[e] = __float2half_rn(Whh[src]);
    }
}
__global__ void prep_misc(const float* __restrict__ h0, const float* __restrict__ Wfc) {
    int i = blockIdx.x * blockDim.x + threadIdx.x;
    int stride = gridDim.x * blockDim.x;
    for (int e = i; e < NCTA * 8 * HID; e += stride) {
        int k = e & (HID - 1);
        int u = (e >> 10) & 7;
        int cta = e >> 13;
        g_Wfc_p[e] = __float2half_rn(Wfc[(size_t)(cta * 8 + u) * HID + k]);
    }
    for (int e = i; e < BATCH * HID; e += stride) g_x0[e] = __float2half_rn(h0[e]);
    for (int e = i; e < 4 * BATCH * HID; e += stride) g_hbuf[e] = __float2half_rn(0.0f);
    if (i == 0) g_bar = 0;
}

// ---------------- split grid barrier ---------------------------------------
__device__ __forceinline__ void gbar_arrive() {
    __threadfence();
    __syncthreads();
    if (threadIdx.x == 0) atomicAdd(&g_bar, 1u);
}
__device__ __forceinline__ void gbar_wait(unsigned target) {
    if (threadIdx.x == 0) {
        unsigned v;
        do {
            asm volatile("ld.acquire.gpu.u32 %0, [%1];" : "=r"(v) : "l"(&g_bar));
        } while (v < target);
    }
    __syncthreads();
}

// ---------------- staging ---------------------------------------------------
__device__ __forceinline__ void stage_act(__half* dst, const __half* src, int k0, int tid) {
    #pragma unroll
    for (int i = 0; i < 4; i++) {
        int e = tid + i * THREADS;          // 1024 ops: 64 rows x 16 segs
        int r = e >> 4, sg = e & 15;
        cp16cg(dst + r * SA + sg * 8, src + r * HID + k0 + sg * 8);
    }
}
__device__ __forceinline__ void stage_w(__half* dst, const __half* src, int k0, int tid) {
    #pragma unroll
    for (int i = 0; i < 2; i++) {
        int e = tid + i * THREADS;          // 512 ops: 32 rows x 16 segs
        int r = e >> 4, sg = e & 15;
        cp16(dst + r * SW + sg * 8, src + r * HID + k0 + sg * 8);
    }
}

// ---------------- main persistent kernel ------------------------------------
__global__ __launch_bounds__(THREADS, 1) void lstm_persist(
    const float* __restrict__ bih, const float* __restrict__ bhh,
    const float* __restrict__ bfc, float* __restrict__ out)
{
    extern __shared__ __align__(16) unsigned char smem_raw[];
    __half* whhS  = (__half*)smem_raw;            // [2][32][SR]
    __half* wfcS  = whhS + 2 * 32 * SR;           // [8][SR]
    __half* xbufS = wfcS + 8 * SR;                // [2][64][SA]
    __half* wbufS = xbufS + 2 * 64 * SA;          // [2][32][SW]
    float*  cS    = (float*)(wbufS + 2 * 32 * SW);// [2][64][8]
    float*  biasS = cS + 2 * 64 * 8;              // [2][32]
    float*  fcbS  = biasS + 64;                   // [8]
    float*  redS  = fcbS + 8;                     // [4][32][4] FC cross-wn reduce

    const int tid  = threadIdx.x;
    const int warp = tid >> 5;
    const int lane = tid & 31;
    const int wm   = warp & 3;     // M-tile
    const int wn   = warp >> 2;    // N-tile (unit group)
    const int cta  = blockIdx.x;
    const int j0   = cta * 8;

    // ---- load resident weights (Whh both layers + Wfc slice) ----
    for (int l = 0; l < 2; l++) {
        const __half* src = g_Whh_p + (size_t)(l * NCTA + cta) * 32 * HID;
        for (int i = 0; i < 16; i++) {
            int e = tid + i * THREADS;      // 32 rows x 128 segs
            int r = e >> 7, sg = e & 127;
            cp16(whhS + l * 32 * SR + r * SR + sg * 8, src + r * HID + sg * 8);
        }
    }
    {
        const __half* src = g_Wfc_p + (size_t)cta * 8 * HID;
        for (int i = 0; i < 4; i++) {
            int e = tid + i * THREADS;      // 8 rows x 128 segs
            int r = e >> 7, sg = e & 127;
            cp16(wfcS + r * SR + sg * 8, src + r * HID + sg * 8);
        }
    }
    cp_commit();
    // ---- biases / cell state ----
    if (tid < 64) {
        int l = tid >> 5, pn = tid & 31;
        int nn = pn & 15, half = nn >> 3, a = (nn & 7) >> 1, s = nn & 1;
        int gate = half * 2 + s, unit = (pn >> 4) * 4 + a;
        int row = gate * HID + j0 + unit;
        biasS[l * 32 + pn] = bih[l * 4 * HID + row] + bhh[l * 4 * HID + row];
    }
    if (tid < 8) fcbS[tid] = bfc[j0 + tid];
    #pragma unroll
    for (int i = 0; i < 4; i++) cS[tid + i * THREADS] = 0.0f;
    cp_wait<0>();
    __syncthreads();

    // precomputed shared addresses (bytes)
    const unsigned xb0 = sptr(xbufS) + ((wm * 16 + (lane & 15)) * SA + (lane >> 4) * 8) * 2;
    const unsigned xb1 = xb0 + 64 * SA * 2;
    const unsigned wb0 = sptr(wbufS) + ((wn * 16 + (lane & 15)) * SW + (lane >> 4) * 8) * 2;
    const unsigned wb1 = wb0 + 32 * SW * 2;
    const unsigned whA[2] = {
        sptr(whhS) + ((wn * 16 + (lane & 15)) * SR + (lane >> 4) * 8) * 2,
        sptr(whhS) + ((32 + wn * 16 + (lane & 15)) * SR + (lane >> 4) * 8) * 2 };
    const unsigned fcA = sptr(wfcS) + (((lane & 7)) * SR + ((lane >> 3) & 1) * 8) * 2;

    unsigned barTarget = 0;
    const int r = lane >> 2, a4 = lane & 3;
    const int uloc = wn * 4 + a4;

    for (int t = 0; t < TSTEPS; t++) {
        const int p = t & 1, q = p ^ 1;
        #pragma unroll 1
        for (int l = 0; l < 2; l++) {
            const __half* xsrc = (l == 0)
                ? ((t == 0) ? g_x0 : g_hbuf + (2 + q) * BATCH * HID)
                : g_hbuf + (0 + p) * BATCH * HID;
            const __half* hsrc = g_hbuf + (l * 2 + q) * BATCH * HID;
            __half* hdst = g_hbuf + (l * 2 + p) * BATCH * HID;
            const __half* wsrc = g_Wih_p + (size_t)(l * NCTA + cta) * 32 * HID;
            const bool fc_phase = (l == 0) && (t > 0);

            // 4 independent accumulation chains (even/odd k16) shared by
            // both GEMM parts (gates = x@Wih + h@Whh).
            float acc0[2][4] = {{0,0,0,0},{0,0,0,0}};
            float acc1[2][4] = {{0,0,0,0},{0,0,0,0}};
            float fca[4] = {0, 0, 0, 0};

            // ===== part A: h_rec @ Whh (resident weights; no barrier needed:
            //       hsrc was written two phases ago). Also prefetch Wih kc0.
            stage_act(xbufS, hsrc, 0, tid);
            stage_w(wbufS, wsrc, 0, tid);
            cp_commit();
            #pragma unroll 1
            for (int kc = 0; kc < HID / KC; kc++) {
                if (kc + 1 < HID / KC) {
                    stage_act(xbufS + ((kc + 1) & 1) * 64 * SA, hsrc, (kc + 1) * KC, tid);
                    cp_commit();
                    cp_wait<1>();
                } else cp_wait<0>();
                __syncthreads();
                const unsigned xb = (kc & 1) ? xb1 : xb0;
                #pragma unroll
                for (int k16 = 0; k16 < KC / 16; k16++) {
                    const int e = k16 & 1;
                    unsigned a0, a1, a2, a3, b0, b1, b2, b3;
                    ldsm_x4(a0, a1, a2, a3, xb + k16 * 32);
                    ldsm_x4(b0, b1, b2, b3, whA[l] + (kc * KC + k16 * 16) * 2);
                    hmma(acc0[e], a0, a1, a2, a3, b0, b2);
                    hmma(acc1[e], a0, a1, a2, a3, b1, b3);
                }
                __syncthreads();
            }

            // ===== barrier wait (mostly satisfied already) =====
            gbar_wait(barTarget);

            // ===== part B: x @ Wih (streamed) + FC (k-split across wn) =====
            stage_act(xbufS, xsrc, 0, tid);
            cp_commit();
            #pragma unroll 1
            for (int kc = 0; kc < HID / KC; kc++) {
                if (kc + 1 < HID / KC) {
                    stage_act(xbufS + ((kc + 1) & 1) * 64 * SA, xsrc, (kc + 1) * KC, tid);
                    stage_w(wbufS + ((kc + 1) & 1) * 32 * SW, wsrc, (kc + 1) * KC, tid);
                    cp_commit();
                    cp_wait<1>();
                } else cp_wait<0>();
                __syncthreads();
                const unsigned xb = (kc & 1) ? xb1 : xb0;
                const unsigned wb = (kc & 1) ? wb1 : wb0;
                #pragma unroll
                for (int k16 = 0; k16 < KC / 16; k16++) {
                    const int e = k16 & 1;
                    unsigned a0, a1, a2, a3, b0, b1, b2, b3;
                    ldsm_x4(a0, a1, a2, a3, xb + k16 * 32);
                    ldsm_x4(b0, b1, b2, b3, wb + k16 * 32);
                    hmma(acc0[e], a0, a1, a2, a3, b0, b2);
                    hmma(acc1[e], a0, a1, a2, a3, b1, b3);
                    if (fc_phase && e == wn) {
                        unsigned f0, f1;
                        ldsm_x2(f0, f1, fcA + (kc * KC + k16 * 16) * 2);
                        hmma(fca, a0, a1, a2, a3, f0, f1);
                    }
                }
                __syncthreads();
            }

            // ===== epilogue: register-local cell update =====
            float* crow = cS + l * 64 * 8;
            #pragma unroll
            for (int rp = 0; rp < 2; rp++) {
                int b = wm * 16 + r + rp * 8;
                int k = rp * 2;
                float iv = acc0[0][k+0] + acc0[1][k+0] + biasS[l * 32 + wn * 16 + a4 * 2 + 0];
                float fv = acc0[0][k+1] + acc0[1][k+1] + biasS[l * 32 + wn * 16 + a4 * 2 + 1];
                float gv = acc1[0][k+0] + acc1[1][k+0] + biasS[l * 32 + wn * 16 + 8 + a4 * 2 + 0];
                float ov = acc1[0][k+1] + acc1[1][k+1] + biasS[l * 32 + wn * 16 + 8 + a4 * 2 + 1];
                float cn = sig_(fv) * crow[b * 8 + uloc] + sig_(iv) * tanhf(gv);
                crow[b * 8 + uloc] = cn;
                hdst[b * HID + j0 + uloc] = __float2half_rn(sig_(ov) * tanhf(cn));
            }
            if (fc_phase) {
                // cross-wn FC reduction: wn1 -> SMEM, wn0 adds + stores
                if (wn == 1) {
                    #pragma unroll
                    for (int i = 0; i < 4; i++) redS[(wm * 32 + lane) * 4 + i] = fca[i];
                }
                __syncthreads();
                if (wn == 0) {
                    float* op = out + (size_t)(t - 1) * BATCH * HID;
                    #pragma unroll
                    for (int rp = 0; rp < 2; rp++) {
                        int b = wm * 16 + r + rp * 8;
                        int k = rp * 2;
                        float v0 = fca[k+0] + redS[(wm * 32 + lane) * 4 + k + 0] + fcbS[a4 * 2 + 0];
                        float v1 = fca[k+1] + redS[(wm * 32 + lane) * 4 + k + 1] + fcbS[a4 * 2 + 1];
                        op[b * HID + j0 + a4 * 2 + 0] = v0;
                        op[b * HID + j0 + a4 * 2 + 1] = v1;
                    }
                }
            }
            gbar_arrive();
            barTarget += NCTA;
        }
    }

    // ===== final FC for t = T-1 (x = h1 written at t=127, parity 1) =====
    {
        gbar_wait(barTarget);
        const __half* xsrc = g_hbuf + (2 + 1) * BATCH * HID;
        float fca[4] = {0, 0, 0, 0};
        stage_act(xbufS, xsrc, 0, tid);
        cp_commit();
        #pragma unroll 1
        for (int kc = 0; kc < HID / KC; kc++) {
            if (kc + 1 < HID / KC) {
                stage_act(xbufS + ((kc + 1) & 1) * 64 * SA, xsrc, (kc + 1) * KC, tid);
                cp_commit();
                cp_wait<1>();
            } else cp_wait<0>();
            __syncthreads();
            const unsigned xb = (kc & 1) ? xb1 : xb0;
            #pragma unroll
            for (int k16 = 0; k16 < KC / 16; k16++) {
                if ((k16 & 1) == wn) {
                    unsigned a0, a1, a2, a3, f0, f1;
                    ldsm_x4(a0, a1, a2, a3, xb + k16 * 32);
                    ldsm_x2(f0, f1, fcA + (kc * KC + k16 * 16) * 2);
                    hmma(fca, a0, a1, a2, a3, f0, f1);
                }
            }
            __syncthreads();
        }
        if (wn == 1) {
            #pragma unroll
            for (int i = 0; i < 4; i++) redS[(wm * 32 + lane) * 4 + i] = fca[i];
        }
        __syncthreads();
        if (wn == 0) {
            float* op = out + (size_t)(TSTEPS - 1) * BATCH * HID;
            #pragma unroll
            for (int rp = 0; rp < 2; rp++) {
                int b = wm * 16 + r + rp * 8;
                int k = rp * 2;
                float v0 = fca[k+0] + redS[(wm * 32 + lane) * 4 + k + 0] + fcbS[a4 * 2 + 0];
                float v1 = fca[k+1] + redS[(wm * 32 + lane) * 4 + k + 1] + fcbS[a4 * 2 + 1];
                op[b * HID + j0 + a4 * 2 + 0] = v0;
                op[b * HID + j0 + a4 * 2 + 1] = v1;
            }
        }
    }
}

// ---------------- host launch -----------------------------------------------
extern "C" void kernel_launch(void* const* d_in, const int* in_sizes, int n_in,
                              void* d_out, int out_size) {
    const float* h0  = (const float*)d_in[0];
    const float* Wih = (const float*)d_in[1];
    const float* Whh = (const float*)d_in[2];
    const float* bih = (const float*)d_in[3];
    const float* bhh = (const float*)d_in[4];
    const float* Wfc = (const float*)d_in[5];
    const float* bfc = (const float*)d_in[6];
    float* out = (float*)d_out;

    const int smem = (2 * 32 * SR + 8 * SR + 2 * 64 * SA + 2 * 32 * SW) * 2
                   + (2 * 64 * 8 + 64 + 8 + 4 * 32 * 4) * 4;
    cudaFuncSetAttribute(lstm_persist, cudaFuncAttributeMaxDynamicSharedMemorySize, smem);

    prep_gatew<<<2048, 256>>>(Wih, Whh);
    prep_misc<<<512, 256>>>(h0, Wfc);
    lstm_persist<<<NCTA, THREADS, smem>>>(bih, bhh, bfc, out);
}